// round 10
// baseline (speedup 1.0000x reference)
#include <cuda_runtime.h>

#define N_NODES 50000
#define N_EDGES 800000
#define IN_F 64
#define D_ATT 64
#define HEADS 8
#define D_HEAD 8

typedef unsigned long long ull;

// Scratch (device globals — no allocation allowed).
// g_q / g_k are stored TRANSPOSED within each 64-wide row: [node][d*8 + h],
// so each head-dim d's 8 values are contiguous (one 32B span).
__device__ __align__(16) float g_q[N_NODES * D_ATT];
__device__ __align__(16) float g_k[N_NODES * D_ATT];
__device__ __align__(16) float g_sum[N_NODES * D_HEAD];
// k-quad-interleaved weights:
// g_wp4[mat][k4*64 + c] = (W[4k4][c], W[4k4+1][c], W[4k4+2][c], W[4k4+3][c])
__device__ __align__(16) float4 g_wp4[3][16 * 64];

// ---------- f32x2 helpers (sm_103a packed FFMA2) ----------
__device__ __forceinline__ void unpack2(ull v, float& lo, float& hi) {
    asm("mov.b64 {%0, %1}, %2;" : "=f"(lo), "=f"(hi) : "l"(v));
}
__device__ __forceinline__ ull fma2(ull a, ull b, ull c) {
    ull d;
    asm("fma.rn.f32x2 %0, %1, %2, %3;" : "=l"(d) : "l"(a), "l"(b), "l"(c));
    return d;
}
__device__ __forceinline__ ull pk2(float x, float y) {
    ull r;
    asm("mov.b64 %0, {%1, %2};" : "=l"(r) : "f"(x), "f"(y));
    return r;
}

// Interleave W into k-quad float4 layout (runs once, ~1us).
__global__ void prep_kernel(const float* __restrict__ Wq,
                            const float* __restrict__ Wk,
                            const float* __restrict__ Wv) {
    int i = blockIdx.x * blockDim.x + threadIdx.x;  // 0..3071
    if (i >= 3 * 16 * 64) return;
    int mat = i >> 10, r = i & 1023;
    int k4 = r >> 6, c = r & 63;
    const float* W = (mat == 0) ? Wq : (mat == 1) ? Wk : Wv;
    g_wp4[mat][r] = make_float4(W[(4 * k4 + 0) * D_ATT + c],
                                W[(4 * k4 + 1) * D_ATT + c],
                                W[(4 * k4 + 2) * D_ATT + c],
                                W[(4 * k4 + 3) * D_ATT + c]);
}

#define XS_STRIDE 68      // padded row stride (floats), 16B-aligned rows
#define PROJ_GRID 444     // exactly 3 CTAs/SM at ~80 regs (reg-limited occupancy)
#define N_TILES ((N_NODES + 31) / 32)

// Fused Q/K/V projection (+ zeroing of g_sum).
// Persistent blocks grid-stride over 32-row tiles. Block = (64, 4) threads.
// x staged row-major in smem (LDS.128 broadcast reads); weights read as k-quad
// float4 from L1-resident global scratch (LDG.128, lanes contiguous).
// Accumulators are f32x2 packed over the k axis (horizontal add at the end).
// Thread column = tx (coalesced weight loads + v store); head-transpose
// permutation applied at the q/k STORE index (still one 256B row per warp).
__global__ void __launch_bounds__(256, 3)
proj_kernel(const float* __restrict__ x,
            const float* __restrict__ bq, const float* __restrict__ bk,
            const float* __restrict__ bv, float* __restrict__ v_out) {
    __shared__ float xs[32][XS_STRIDE];
    const int tx = threadIdx.x;      // 0..63 = original output column
    const int rg = threadIdx.y;      // 0..3
    const int tid = rg * 64 + tx;
    const int pc = ((tx & 7) << 3) | (tx >> 3);  // transposed position of col tx

    // Zero g_sum (grid-stride)
    for (int zi = blockIdx.x * 256 + tid; zi < N_NODES * D_HEAD; zi += PROJ_GRID * 256)
        g_sum[zi] = 0.0f;

    const float4* wq_p = &g_wp4[0][tx];
    const float4* wk_p = &g_wp4[1][tx];
    const float4* wv_p = &g_wp4[2][tx];
    const float bqv = __ldg(&bq[tx]), bkv = __ldg(&bk[tx]), bvv = __ldg(&bv[tx]);

    for (int tile = blockIdx.x; tile < N_TILES; tile += PROJ_GRID) {
        const int row0 = tile * 32;
        __syncthreads();  // xs from previous tile fully consumed
        // Stage x tile row-major (coalesced read)
        for (int i = tid; i < 32 * IN_F; i += 256) {
            int r = i >> 6, kk = i & 63;
            int grow = row0 + r;
            xs[r][kk] = (grow < N_NODES) ? x[grow * IN_F + kk] : 0.0f;
        }
        __syncthreads();

        ull aq[8], ak[8], av[8];
#pragma unroll
        for (int i = 0; i < 8; i++) { aq[i] = 0ull; ak[i] = 0ull; av[i] = 0ull; }

        const float* x_base = &xs[rg * 8][0];

#pragma unroll 4
        for (int k4 = 0; k4 < IN_F / 4; k4++) {
            float4 wq = __ldg(&wq_p[k4 * 64]);   // LDG.128, lanes contiguous
            float4 wk = __ldg(&wk_p[k4 * 64]);
            float4 wv = __ldg(&wv_p[k4 * 64]);
            ull wq_lo = pk2(wq.x, wq.y), wq_hi = pk2(wq.z, wq.w);
            ull wk_lo = pk2(wk.x, wk.y), wk_hi = pk2(wk.z, wk.w);
            ull wv_lo = pk2(wv.x, wv.y), wv_hi = pk2(wv.z, wv.w);
#pragma unroll
            for (int i = 0; i < 8; i++) {
                float4 xq = *(const float4*)&x_base[i * XS_STRIDE + 4 * k4];  // LDS.128 bcast
                ull x_lo = pk2(xq.x, xq.y), x_hi = pk2(xq.z, xq.w);
                aq[i] = fma2(x_lo, wq_lo, aq[i]);
                aq[i] = fma2(x_hi, wq_hi, aq[i]);
                ak[i] = fma2(x_lo, wk_lo, ak[i]);
                ak[i] = fma2(x_hi, wk_hi, ak[i]);
                av[i] = fma2(x_lo, wv_lo, av[i]);
                av[i] = fma2(x_hi, wv_hi, av[i]);
            }
        }

#pragma unroll
        for (int i = 0; i < 8; i++) {
            int r = row0 + rg * 8 + i;
            if (r < N_NODES) {
                float lo, hi;
                unpack2(aq[i], lo, hi);
                g_q[r * D_ATT + pc] = lo + hi + bqv;
                unpack2(ak[i], lo, hi);
                g_k[r * D_ATT + pc] = lo + hi + bkv;
                unpack2(av[i], lo, hi);
                v_out[r * D_ATT + tx] = lo + hi + bvv;
            }
        }
    }
}

// Cooperative edge kernel: 8 lanes per edge.
// Lane j loads the CONTIGUOUS float4 at byte offset j*16 of the q/k rows
// (one 128B line per LDG.128 per edge). Elements j*4..j*4+3 all belong to
// head-dim d = j>>1: 4-wide partial dot + one shfl_xor(1) finishes each dot.
// Lane j then owns one (d, exp): 1 exp, 1 prods store, 1 att store per lane.
// Four shuffles gather the 8 exps into lanes 0/1, which issue two
// red.global.add.v4.f32 into g_sum. Max-subtraction omitted: softmax ratio is
// shift-invariant; logits ~N(0,3) cannot overflow fp32 exp.
__global__ void edge_kernel(const int* __restrict__ e0, const int* __restrict__ e1,
                            float* __restrict__ att_out, float* __restrict__ prods_out) {
    const int idx = blockIdx.x * blockDim.x + threadIdx.x;  // grid exact: N_EDGES*8
    const int e = idx >> 3;
    const int lane = threadIdx.x & 31;
    const int j = lane & 7;
    const int grp = lane & ~7;

    const int s = e0[e];
    const int t = e1[e];

    const float4* qp = (const float4*)(g_q + s * D_ATT);
    const float4* kp = (const float4*)(g_k + t * D_ATT);
    float4 q0 = qp[j];
    float4 q1 = qp[8 + j];
    float4 k0 = kp[j];
    float4 k1 = kp[8 + j];

    float p0 = q0.x * k0.x;
    p0 = fmaf(q0.y, k0.y, p0);
    p0 = fmaf(q0.z, k0.z, p0);
    p0 = fmaf(q0.w, k0.w, p0);
    float p1 = q1.x * k1.x;
    p1 = fmaf(q1.y, k1.y, p1);
    p1 = fmaf(q1.z, k1.z, p1);
    p1 = fmaf(q1.w, k1.w, p1);

    p0 += __shfl_xor_sync(0xffffffffu, p0, 1);
    p1 += __shfl_xor_sync(0xffffffffu, p1, 1);

    const float c = 0.35355339059327373f;  // 1/sqrt(8)
    const int m = j >> 1;
    const int odd = j & 1;
    const int d = odd ? (4 + m) : m;
    const float p = (odd ? p1 : p0) * c;

    const int oidx = e * D_HEAD + d;
    prods_out[oidx] = p;
    const float ex = __expf(p);
    att_out[oidx] = ex;

    float r0 = __shfl_sync(0xffffffffu, ex, grp + odd);
    float r1 = __shfl_sync(0xffffffffu, ex, grp + odd + 2);
    float r2 = __shfl_sync(0xffffffffu, ex, grp + odd + 4);
    float r3 = __shfl_sync(0xffffffffu, ex, grp + odd + 6);
    if (j < 2) {
        float* dst = &g_sum[t * D_HEAD + j * 4];  // 16B aligned
        asm volatile("red.global.add.v4.f32 [%0], {%1, %2, %3, %4};"
                     :: "l"(dst), "f"(r0), "f"(r1), "f"(r2), "f"(r3)
                     : "memory");
    }
}

// Convert sums to reciprocals in place: g_sum[i] = 1/(g_sum[i]+eps).
// Moves the MUFU divide cost out of norm's critical path (~400K values).
__global__ void recip_kernel() {
    int i = blockIdx.x * blockDim.x + threadIdx.x;
    if (i >= N_NODES * D_HEAD / 4) return;
    float4 s = ((const float4*)g_sum)[i];
    s.x = __frcp_rn(s.x + 1e-16f);
    s.y = __frcp_rn(s.y + 1e-16f);
    s.z = __frcp_rn(s.z + 1e-16f);
    s.w = __frcp_rn(s.w + 1e-16f);
    ((float4*)g_sum)[i] = s;
}

// One thread per edge; multiplies by precomputed reciprocals (no MUFU).
__global__ void norm_kernel(const int* __restrict__ e1, float* __restrict__ att) {
    int e = blockIdx.x * blockDim.x + threadIdx.x;
    if (e >= N_EDGES) return;
    int t = e1[e];
    float4* att4 = (float4*)att;
    const float4* sum4 = (const float4*)g_sum;
    float4 a0 = att4[e * 2], a1 = att4[e * 2 + 1];
    float4 s0 = sum4[t * 2], s1 = sum4[t * 2 + 1];
    a0.x *= s0.x;
    a0.y *= s0.y;
    a0.z *= s0.z;
    a0.w *= s0.w;
    a1.x *= s1.x;
    a1.y *= s1.y;
    a1.z *= s1.z;
    a1.w *= s1.w;
    att4[e * 2] = a0;
    att4[e * 2 + 1] = a1;
}

extern "C" void kernel_launch(void* const* d_in, const int* in_sizes, int n_in,
                              void* d_out, int out_size) {
    const float* x  = (const float*)d_in[0];
    const float* Wq = (const float*)d_in[1];
    const float* bq = (const float*)d_in[2];
    const float* Wk = (const float*)d_in[3];
    const float* bk = (const float*)d_in[4];
    const float* Wv = (const float*)d_in[5];
    const float* bv = (const float*)d_in[6];
    const int* edge = (const int*)d_in[7];

    float* out   = (float*)d_out;
    float* att   = out;                                   // [E, 8]
    float* v_out = out + (size_t)N_EDGES * D_HEAD;        // [N, 64]
    float* prods = v_out + (size_t)N_NODES * D_ATT;       // [E, 8]

    const int* e0 = edge;            // edge[0, :]
    const int* e1 = edge + N_EDGES;  // edge[1, :]

    prep_kernel<<<(3 * 16 * 64 + 255) / 256, 256>>>(Wq, Wk, Wv);
    proj_kernel<<<PROJ_GRID, dim3(64, 4)>>>(x, bq, bk, bv, v_out);
    edge_kernel<<<N_EDGES * 8 / 256, 256>>>(e0, e1, att, prods);
    recip_kernel<<<(N_NODES * D_HEAD / 4 + 255) / 256, 256>>>();
    norm_kernel<<<(N_EDGES + 255) / 256, 256>>>(e1, att);
}